// round 1
// baseline (speedup 1.0000x reference)
#include <cuda_runtime.h>
#include <cuda_bf16.h>

#define BB 4
#define NN 8192
#define HH 8
#define DD 64
#define BH (BB*HH)

#define P1_CHUNK 512   // rows per phase-1 block
#define TILE_R   32    // rows per smem tile in phase 1
#define P2_CHUNK 256   // rows per phase-2 block
#define TILE_N   64    // rows per smem tile in phase 2

// Scratch: KV[bh][m][d] and Ksum[bh][d]
__device__ float g_KV[BH][DD][DD];
__device__ float g_Ksum[BH][DD];

__device__ __forceinline__ float elu1(float x) {
    // elu(x) + 1 = x + 1 (x > 0), exp(x) (x <= 0)
    return x > 0.f ? x + 1.f : __expf(x);
}

__global__ void zero_scratch_kernel() {
    int i = blockIdx.x * blockDim.x + threadIdx.x;
    if (i < BH * DD * DD) (&g_KV[0][0][0])[i] = 0.f;
    if (i < BH * DD)      (&g_Ksum[0][0])[i]  = 0.f;
}

// ---------------------------------------------------------------------------
// Phase 1: KV[bh][m][d] += sum_n V[n][m] * K[n][d];  Ksum[bh][d] += sum_n K[n][d]
// grid: (BH, NN/P1_CHUNK), block: 256
// ---------------------------------------------------------------------------
__global__ __launch_bounds__(256) void phase1_kernel(
    const float* __restrict__ Kg,
    const float* __restrict__ Vg,
    const float* __restrict__ maskg)
{
    __shared__ __align__(16) float Ks[TILE_R][DD];
    __shared__ __align__(16) float Vs[TILE_R][DD];

    const int bh = blockIdx.x;
    const int chunk = blockIdx.y;
    const int b = bh / HH, h = bh % HH;
    const int t = threadIdx.x;
    const int mi = t >> 4, di = t & 15;
    const int m0 = mi * 4, d0 = di * 4;

    const size_t base = (size_t)b * NN * HH * DD + (size_t)h * DD;

    float acc[4][4] = {};
    float ksum = 0.f;

    const int n_begin = chunk * P1_CHUNK;
    const int n_end   = n_begin + P1_CHUNK;

    for (int n0 = n_begin; n0 < n_end; n0 += TILE_R) {
        __syncthreads();
        // Load TILE_R rows of K (with elu+mask) and V: 512 float4 each half-set
        #pragma unroll
        for (int i = 0; i < 2; ++i) {
            int idx = t + i * 256;          // 0..511
            int r = idx >> 4;               // 0..31
            int c = (idx & 15) * 4;         // 0..60
            int n = n0 + r;
            const size_t roff = base + (size_t)n * (HH * DD) + c;
            float msk = maskg[b * NN + n];
            float4 k4 = *(const float4*)(Kg + roff);
            float4 kf;
            kf.x = elu1(k4.x) * msk;
            kf.y = elu1(k4.y) * msk;
            kf.z = elu1(k4.z) * msk;
            kf.w = elu1(k4.w) * msk;
            *(float4*)&Ks[r][c] = kf;
            float4 v4 = *(const float4*)(Vg + roff);
            *(float4*)&Vs[r][c] = v4;
        }
        __syncthreads();

        #pragma unroll 8
        for (int r = 0; r < TILE_R; ++r) {
            float4 kk = *(const float4*)&Ks[r][d0];
            float4 vv = *(const float4*)&Vs[r][m0];
            float kf[4] = {kk.x, kk.y, kk.z, kk.w};
            float vf[4] = {vv.x, vv.y, vv.z, vv.w};
            #pragma unroll
            for (int a = 0; a < 4; ++a)
                #pragma unroll
                for (int c = 0; c < 4; ++c)
                    acc[a][c] += vf[a] * kf[c];
        }
        if (t < DD) {
            #pragma unroll 8
            for (int r = 0; r < TILE_R; ++r) ksum += Ks[r][t];
        }
    }

    #pragma unroll
    for (int a = 0; a < 4; ++a)
        #pragma unroll
        for (int c = 0; c < 4; ++c)
            atomicAdd(&g_KV[bh][m0 + a][d0 + c], acc[a][c]);
    if (t < DD) atomicAdd(&g_Ksum[bh][t], ksum);
}

// ---------------------------------------------------------------------------
// Phase 2: out[n][m] = (1/(Q[n].Ksum + eps)) * sum_d Q[n][d] * KV[m][d]
// grid: (BH, NN/P2_CHUNK), block: 256
// ---------------------------------------------------------------------------
__global__ __launch_bounds__(256) void phase2_kernel(
    const float* __restrict__ Qg,
    float* __restrict__ Og)
{
    __shared__ __align__(16) float KVT[DD][68];   // [d][m], padded stride
    __shared__ __align__(16) float Ksm[DD];
    __shared__ __align__(16) float Qs[TILE_N][68];
    __shared__ float zs[TILE_N];

    const int bh = blockIdx.x;
    const int chunk = blockIdx.y;
    const int b = bh / HH, h = bh % HH;
    const int t = threadIdx.x;
    const int ni = t >> 4, mi = t & 15;
    const int m0 = mi * 4;

    // Load KV transposed into smem: KVT[d][m] = g_KV[bh][m][d]
    for (int i = t; i < DD * DD; i += 256) {
        int m = i >> 6, d = i & 63;
        KVT[d][m] = g_KV[bh][m][d];
    }
    if (t < DD) Ksm[t] = g_Ksum[bh][t];

    const size_t base = (size_t)b * NN * HH * DD + (size_t)h * DD;
    const int n_begin = chunk * P2_CHUNK;
    const int n_end   = n_begin + P2_CHUNK;

    for (int n0 = n_begin; n0 < n_end; n0 += TILE_N) {
        __syncthreads();
        // Load 64 rows of Q (with elu): 1024 float4, 4 per thread
        #pragma unroll
        for (int i = 0; i < 4; ++i) {
            int idx = t + i * 256;
            int r = idx >> 4;           // 0..63
            int c = (idx & 15) * 4;
            const size_t roff = base + (size_t)(n0 + r) * (HH * DD) + c;
            float4 q4 = *(const float4*)(Qg + roff);
            q4.x = elu1(q4.x);
            q4.y = elu1(q4.y);
            q4.z = elu1(q4.z);
            q4.w = elu1(q4.w);
            *(float4*)&Qs[r][c] = q4;
        }
        __syncthreads();

        float acc[4][4] = {};
        float den[4] = {};

        #pragma unroll 8
        for (int d = 0; d < DD; d += 4) {
            float4 kv0 = *(const float4*)&KVT[d + 0][m0];
            float4 kv1 = *(const float4*)&KVT[d + 1][m0];
            float4 kv2 = *(const float4*)&KVT[d + 2][m0];
            float4 kv3 = *(const float4*)&KVT[d + 3][m0];
            float kvf[4][4] = {
                {kv0.x, kv0.y, kv0.z, kv0.w},
                {kv1.x, kv1.y, kv1.z, kv1.w},
                {kv2.x, kv2.y, kv2.z, kv2.w},
                {kv3.x, kv3.y, kv3.z, kv3.w}};
            float4 ks4;
            if (mi == 0) ks4 = *(const float4*)&Ksm[d];
            #pragma unroll
            for (int a = 0; a < 4; ++a) {
                float4 q4 = *(const float4*)&Qs[ni * 4 + a][d];
                float qf[4] = {q4.x, q4.y, q4.z, q4.w};
                #pragma unroll
                for (int j = 0; j < 4; ++j)
                    #pragma unroll
                    for (int c = 0; c < 4; ++c)
                        acc[a][c] += qf[j] * kvf[j][c];
                if (mi == 0) {
                    den[a] += qf[0] * ks4.x;
                    den[a] += qf[1] * ks4.y;
                    den[a] += qf[2] * ks4.z;
                    den[a] += qf[3] * ks4.w;
                }
            }
        }

        if (mi == 0) {
            #pragma unroll
            for (int a = 0; a < 4; ++a)
                zs[ni * 4 + a] = 1.f / (den[a] + 1e-6f);
        }
        __syncthreads();

        #pragma unroll
        for (int a = 0; a < 4; ++a) {
            float z = zs[ni * 4 + a];
            float4 o;
            o.x = acc[a][0] * z;
            o.y = acc[a][1] * z;
            o.z = acc[a][2] * z;
            o.w = acc[a][3] * z;
            *(float4*)(Og + base + (size_t)(n0 + ni * 4 + a) * (HH * DD) + m0) = o;
        }
    }
}

extern "C" void kernel_launch(void* const* d_in, const int* in_sizes, int n_in,
                              void* d_out, int out_size) {
    const float* Q    = (const float*)d_in[0];
    const float* K    = (const float*)d_in[1];
    const float* V    = (const float*)d_in[2];
    const float* mask = (const float*)d_in[3];
    float* out = (float*)d_out;

    zero_scratch_kernel<<<(BH * DD * DD + 255) / 256, 256>>>();

    dim3 g1(BH, NN / P1_CHUNK);
    phase1_kernel<<<g1, 256>>>(K, V, mask);

    dim3 g2(BH, NN / P2_CHUNK);
    phase2_kernel<<<g2, 256>>>(Q, out);
}

// round 3
// speedup vs baseline: 1.6357x; 1.6357x over previous
#include <cuda_runtime.h>
#include <cuda_bf16.h>
#include <cstdint>

#define BB 4
#define NN 8192
#define HH 8
#define DD 64
#define BH 32
#define RS (HH*DD)        // 512 floats: row stride in global [B,N,H,D]

#define P1_CHUNK 512
#define T1 32             // phase-1 smem n-tile rows
#define S1 72             // phase-1 smem stride (72%32==8 -> bank = 8q+g, conflict-free)

#define T2 128            // phase-2 n-tile rows per block
#define S2 68             // phase-2 smem stride (68%32==4 -> bank = 4g+q, conflict-free)
#define NB 72             // B cols in phase 2: 64 out + 1 den + 7 pad

// Scratch
__device__ float g_KV[BH][DD][DD];
__device__ float g_Ksum[BH][DD];

__device__ __forceinline__ float elu1(float x) {
    return x > 0.f ? x + 1.f : __expf(x);
}
__device__ __forceinline__ uint32_t f2tf(float x) {
    uint32_t u; asm("cvt.rna.tf32.f32 %0, %1;" : "=r"(u) : "f"(x)); return u;
}
__device__ __forceinline__ float tf32r(float x) {
    return __uint_as_float(f2tf(x));
}

// D = A(16x8,row) * B(8x8,col) + D, tf32 inputs, f32 accum
__device__ __forceinline__ void mma8(float* c, const uint32_t* a, const uint32_t* b) {
    asm volatile(
        "mma.sync.aligned.m16n8k8.row.col.f32.tf32.tf32.f32 "
        "{%0,%1,%2,%3}, {%4,%5,%6,%7}, {%8,%9}, {%0,%1,%2,%3};"
        : "+f"(c[0]), "+f"(c[1]), "+f"(c[2]), "+f"(c[3])
        : "r"(a[0]), "r"(a[1]), "r"(a[2]), "r"(a[3]), "r"(b[0]), "r"(b[1]));
}

__global__ void zero_scratch_kernel() {
    int i = blockIdx.x * blockDim.x + threadIdx.x;
    if (i < BH * DD * DD) (&g_KV[0][0][0])[i] = 0.f;
    if (i < BH * DD)      (&g_Ksum[0][0])[i]  = 0.f;
}

// ---------------------------------------------------------------------------
// Phase 1 (mma.sync tf32): KV[m][d] += sum_n V[n][m]*K[n][d]; Ksum[d] += sum K
// grid (BH, NN/P1_CHUNK), block 256 (8 warps)
// Warp w: C rows m = (w&3)*16 .. +15, cols d = (w>>2)*32 .. +31 (4 j-tiles)
// ---------------------------------------------------------------------------
__global__ __launch_bounds__(256) void phase1_kernel(
    const float* __restrict__ Kg,
    const float* __restrict__ Vg,
    const float* __restrict__ maskg)
{
    __shared__ float Ks[T1][S1];
    __shared__ float Vs[T1][S1];

    const int bh = blockIdx.x, b = bh >> 3, h = bh & 7;
    const int t = threadIdx.x;
    const int w = t >> 5, lane = t & 31, g = lane >> 2, q = lane & 3;
    const int mrow = (w & 3) * 16;
    const int dcol = (w >> 2) * 32;

    const size_t base = (size_t)b * NN * RS + (size_t)h * DD;

    float acc[4][4] = {};
    float ksum = 0.f;

    const int n_beg = blockIdx.y * P1_CHUNK;
    for (int n0 = n_beg; n0 < n_beg + P1_CHUNK; n0 += T1) {
        __syncthreads();
        #pragma unroll
        for (int i = 0; i < 2; ++i) {
            int idx = t + i * 256;
            int r = idx >> 4, c = (idx & 15) * 4;
            const size_t off = base + (size_t)(n0 + r) * RS + c;
            float msk = maskg[b * NN + n0 + r];
            float4 k4 = *(const float4*)(Kg + off);
            Ks[r][c + 0] = tf32r(elu1(k4.x) * msk);
            Ks[r][c + 1] = tf32r(elu1(k4.y) * msk);
            Ks[r][c + 2] = tf32r(elu1(k4.z) * msk);
            Ks[r][c + 3] = tf32r(elu1(k4.w) * msk);
            float4 v4 = *(const float4*)(Vg + off);
            Vs[r][c + 0] = tf32r(v4.x);
            Vs[r][c + 1] = tf32r(v4.y);
            Vs[r][c + 2] = tf32r(v4.z);
            Vs[r][c + 3] = tf32r(v4.w);
        }
        __syncthreads();

        #pragma unroll
        for (int ks = 0; ks < 4; ++ks) {
            const int n = ks * 8;
            uint32_t a[4];
            // A[m, n] = Vs[n][m]; frag: a0(g,q) a1(g+8,q) a2(g,q+4) a3(g+8,q+4)
            a[0] = __float_as_uint(Vs[n + q][mrow + g]);
            a[1] = __float_as_uint(Vs[n + q][mrow + 8 + g]);
            a[2] = __float_as_uint(Vs[n + 4 + q][mrow + g]);
            a[3] = __float_as_uint(Vs[n + 4 + q][mrow + 8 + g]);
            #pragma unroll
            for (int j = 0; j < 4; ++j) {
                uint32_t bf[2];
                // B[n, d] = Ks[n][d]; frag: b0(q, g) b1(q+4, g)
                bf[0] = __float_as_uint(Ks[n + q][dcol + j * 8 + g]);
                bf[1] = __float_as_uint(Ks[n + 4 + q][dcol + j * 8 + g]);
                mma8(acc[j], a, bf);
            }
        }
        if (t < DD) {
            #pragma unroll
            for (int r = 0; r < T1; ++r) ksum += Ks[r][t];
        }
    }

    #pragma unroll
    for (int j = 0; j < 4; ++j) {
        const int col = dcol + j * 8 + 2 * q;
        atomicAdd(&g_KV[bh][mrow + g][col],         acc[j][0]);
        atomicAdd(&g_KV[bh][mrow + g][col + 1],     acc[j][1]);
        atomicAdd(&g_KV[bh][mrow + 8 + g][col],     acc[j][2]);
        atomicAdd(&g_KV[bh][mrow + 8 + g][col + 1], acc[j][3]);
    }
    if (t < DD) atomicAdd(&g_Ksum[bh][t], ksum);
}

// ---------------------------------------------------------------------------
// Phase 2 (mma.sync tf32):
//   C[n, 0:64] = Qf[n,:]·KV[m,:] ; C[n,64] = Qf[n,:]·Ksum (den)
//   out[n,m] = C[n,m] / (C[n,64] + eps)
// grid (BH, NN/T2), block 256 (8 warps). Warp w: rows w*16..+15, all 72 cols.
// ---------------------------------------------------------------------------
extern __shared__ float sm2[];   // Qs[T2][S2] then KVs[NB][S2]

__global__ __launch_bounds__(256) void phase2_kernel(
    const float* __restrict__ Qg,
    float* __restrict__ Og)
{
    float (*Qs)[S2]  = (float (*)[S2])sm2;
    float (*KVs)[S2] = (float (*)[S2])(sm2 + T2 * S2);

    const int bh = blockIdx.x, b = bh >> 3, h = bh & 7;
    const int t = threadIdx.x;
    const int w = t >> 5, lane = t & 31, g = lane >> 2, q = lane & 3;
    const int r0 = w * 16;

    // Fill B: KV rows 0..63 (tf32), Ksum row 64, zeros 65..71
    for (int i = t; i < DD * DD; i += 256) {
        int m = i >> 6, d = i & 63;
        KVs[m][d] = tf32r(g_KV[bh][m][d]);
    }
    if (t < DD) KVs[DD][t] = tf32r(g_Ksum[bh][t]);
    for (int i = t; i < 7 * DD; i += 256) {
        int m = 65 + (i >> 6), d = i & 63;
        KVs[m][d] = 0.f;
    }

    const size_t base = (size_t)b * NN * RS + (size_t)h * DD;
    const int n0 = blockIdx.y * T2;

    // Load Q tile (elu + tf32 round): 128x64, 8 float4 per thread
    #pragma unroll
    for (int i = 0; i < 8; ++i) {
        int idx = t + i * 256;
        int r = idx >> 4, c = (idx & 15) * 4;
        float4 q4 = *(const float4*)(Qg + base + (size_t)(n0 + r) * RS + c);
        Qs[r][c + 0] = tf32r(elu1(q4.x));
        Qs[r][c + 1] = tf32r(elu1(q4.y));
        Qs[r][c + 2] = tf32r(elu1(q4.z));
        Qs[r][c + 3] = tf32r(elu1(q4.w));
    }
    __syncthreads();

    float acc[9][4] = {};

    #pragma unroll
    for (int ks = 0; ks < 8; ++ks) {
        const int k0 = ks * 8;
        uint32_t a[4];
        // A[n, d] = Qs[n][d]; frag rows g/g+8, cols q/q+4
        a[0] = __float_as_uint(Qs[r0 + g][k0 + q]);
        a[1] = __float_as_uint(Qs[r0 + 8 + g][k0 + q]);
        a[2] = __float_as_uint(Qs[r0 + g][k0 + 4 + q]);
        a[3] = __float_as_uint(Qs[r0 + 8 + g][k0 + 4 + q]);
        #pragma unroll
        for (int j = 0; j < 9; ++j) {
            uint32_t bf[2];
            // B[d, m] = KVs[m][d]; frag: b0(q, g) b1(q+4, g)
            bf[0] = __float_as_uint(KVs[j * 8 + g][k0 + q]);
            bf[1] = __float_as_uint(KVs[j * 8 + g][k0 + 4 + q]);
            mma8(acc[j], a, bf);
        }
    }

    // den = C[:,64] lives in tile j=8 at q==0 (c0: row g, c2: row g+8)
    const int src = lane & ~3;
    float den0 = __shfl_sync(0xffffffffu, acc[8][0], src);
    float den1 = __shfl_sync(0xffffffffu, acc[8][2], src);
    float z0 = 1.f / (den0 + 1e-6f);
    float z1 = 1.f / (den1 + 1e-6f);

    float* row_a = Og + base + (size_t)(n0 + r0 + g) * RS;
    float* row_b = Og + base + (size_t)(n0 + r0 + 8 + g) * RS;
    #pragma unroll
    for (int j = 0; j < 8; ++j) {
        const int col = j * 8 + 2 * q;
        float2 oa = make_float2(acc[j][0] * z0, acc[j][1] * z0);
        float2 ob = make_float2(acc[j][2] * z1, acc[j][3] * z1);
        *(float2*)(row_a + col) = oa;
        *(float2*)(row_b + col) = ob;
    }
}

extern "C" void kernel_launch(void* const* d_in, const int* in_sizes, int n_in,
                              void* d_out, int out_size) {
    const float* Q    = (const float*)d_in[0];
    const float* K    = (const float*)d_in[1];
    const float* V    = (const float*)d_in[2];
    const float* mask = (const float*)d_in[3];
    float* out = (float*)d_out;

    zero_scratch_kernel<<<(BH * DD * DD + 255) / 256, 256>>>();

    dim3 g1(BH, NN / P1_CHUNK);
    phase1_kernel<<<g1, 256>>>(K, V, mask);

    const int smem2 = (T2 * S2 + NB * S2) * sizeof(float);   // ~54.4 KB
    static int attr_done = 0;
    if (!attr_done) {
        cudaFuncSetAttribute(phase2_kernel,
                             cudaFuncAttributeMaxDynamicSharedMemorySize, smem2);
        attr_done = 1;
    }
    dim3 g2(BH, NN / T2);
    phase2_kernel<<<g2, 256, smem2>>>(Q, out);
}